// round 2
// baseline (speedup 1.0000x reference)
#include <cuda_runtime.h>

#define NBLK    128   // nodes per graph block
#define FEAT    32    // feature dim
#define THREADS 128
#define NBATCH  1024

__device__ int g_idx[NBATCH];

// Resolve index dtype defensively: jax often silently downcasts int64->int32.
// Read first 4KB as int32 words (safe under both layouts). If all odd words are
// zero, data is int64 (values < 1024 => high halves all zero); else it's int32.
__global__ void resolve_idx_kernel(const int* __restrict__ raw) {
    __shared__ int odd_nonzero;
    const int t = threadIdx.x;  // 1024 threads
    if (t == 0) odd_nonzero = 0;
    __syncthreads();
    int v = raw[t];
    if ((t & 1) && v != 0) odd_nonzero = 1;   // benign race, same value
    __syncthreads();
    int g = odd_nonzero ? raw[t] : raw[2 * t];
    // clamp as a hard OOB guard
    if (g < 0) g = 0;
    if (g >= 1024) g = 1023;
    g_idx[t] = g;
}

__device__ __forceinline__ unsigned long long pack2(float a, float b) {
    unsigned long long r;
    asm("mov.b64 %0, {%1, %2};" : "=l"(r) : "f"(a), "f"(b));
    return r;
}
__device__ __forceinline__ void fma2(unsigned long long &d, unsigned long long a, unsigned long long b) {
    asm("fma.rn.f32x2 %0, %1, %2, %0;" : "+l"(d) : "l"(a), "l"(b));
}
__device__ __forceinline__ void unpack2(unsigned long long v, float &a, float &b) {
    asm("mov.b64 {%0, %1}, %2;" : "=f"(a), "=f"(b) : "l"(v));
}

// One CTA per batch block: out[128,32] = W[idx[b]] (128x128) @ x[b] (128x32), fp32.
// W staged in SMEM K-major (same as gmem, no transpose) with XOR swizzle on the
// 16B slot: slot' = slot ^ ((i>>3)&7). Copy-in STS.128 is conflict-free; compute
// LDS.128 at fixed slot across i-groups spreads across banks.
__global__ void __launch_bounds__(THREADS, 2) bmm_kernel(
    const float* __restrict__ inp,
    const float* __restrict__ W,
    float* __restrict__ out)
{
    extern __shared__ float smem[];
    float* Ws = smem;                 // 128*128 floats, swizzled, 64KB
    float* xs = smem + NBLK * NBLK;   // 128*32 floats, linear, 16KB

    const int blk = blockIdx.x;
    const int tid = threadIdx.x;

    const int g = g_idx[blk];
    const float4* Wg = (const float4*)(W + (long long)g * (NBLK * NBLK));
    const float4* xg = (const float4*)(inp + (long long)blk * NBLK * FEAT);

    // ---- Stage W: 4096 float4, coalesced LDG.128 -> swizzled STS.128 ----
    #pragma unroll
    for (int it = 0; it < (NBLK * NBLK / 4) / THREADS; ++it) {  // 32 iters
        int q = tid + THREADS * it;        // float4 index
        float4 v = Wg[q];
        int i  = q >> 5;                   // row (whole warp shares i)
        int s  = q & 31;                   // 16B slot within row = lane
        int ss = s ^ ((i >> 3) & 7);       // swizzle
        *(float4*)(Ws + i * NBLK + ss * 4) = v;
    }
    // ---- Stage x: 1024 float4, linear ----
    #pragma unroll
    for (int it = 0; it < (NBLK * FEAT / 4) / THREADS; ++it) {  // 8 iters
        int q = tid + THREADS * it;
        ((float4*)xs)[q] = xg[q];
    }
    __syncthreads();

    // Thread tile: 8 rows (i0..i0+7) x 4 feats (f0..f0+3)
    const int i0 = (tid & 15) * 8;
    const int f0 = (tid >> 4) * 4;
    const int sw = tid & 7;                // == ((i>>3)&7) for all 8 rows of this thread

    unsigned long long acc[8][2];
    #pragma unroll
    for (int j = 0; j < 8; ++j) { acc[j][0] = 0ull; acc[j][1] = 0ull; }

    #pragma unroll 4
    for (int k4 = 0; k4 < NBLK / 4; ++k4) {          // 4 k's per iter
        unsigned long long x2[4][2];
        #pragma unroll
        for (int kk = 0; kk < 4; ++kk) {
            ulonglong2 v = *(const ulonglong2*)(xs + (k4 * 4 + kk) * FEAT + f0);
            x2[kk][0] = v.x; x2[kk][1] = v.y;
        }
        const int ss = (k4 ^ sw) * 4;                 // swizzled slot offset (words)
        #pragma unroll
        for (int j = 0; j < 8; ++j) {
            const int i = i0 + j;
            float4 wv = *(const float4*)(Ws + i * NBLK + ss);  // W[i][4k4..4k4+3]
            unsigned long long w2;
            w2 = pack2(wv.x, wv.x); fma2(acc[j][0], w2, x2[0][0]); fma2(acc[j][1], w2, x2[0][1]);
            w2 = pack2(wv.y, wv.y); fma2(acc[j][0], w2, x2[1][0]); fma2(acc[j][1], w2, x2[1][1]);
            w2 = pack2(wv.z, wv.z); fma2(acc[j][0], w2, x2[2][0]); fma2(acc[j][1], w2, x2[2][1]);
            w2 = pack2(wv.w, wv.w); fma2(acc[j][0], w2, x2[3][0]); fma2(acc[j][1], w2, x2[3][1]);
        }
    }

    // ---- Epilogue: STG.128 per row ----
    const long long obase = (long long)blk * NBLK * FEAT;
    #pragma unroll
    for (int j = 0; j < 8; ++j) {
        float4 o;
        unpack2(acc[j][0], o.x, o.y);
        unpack2(acc[j][1], o.z, o.w);
        *(float4*)(out + obase + (long long)(i0 + j) * FEAT + f0) = o;
    }
}

extern "C" void kernel_launch(void* const* d_in, const int* in_sizes, int n_in,
                              void* d_out, int out_size) {
    // Select pointers by element count (robust to metadata ordering):
    // input: 1024*128*32 = 4194304 fp32; weights: 1024*128*128 = 16777216 fp32;
    // batch_idrange: 1024 (int32 or int64).
    const float* inp = nullptr;
    const float* W   = nullptr;
    const void*  idx = nullptr;
    for (int i = 0; i < n_in; ++i) {
        if      (in_sizes[i] == 4194304)  inp = (const float*)d_in[i];
        else if (in_sizes[i] == 16777216) W   = (const float*)d_in[i];
        else if (in_sizes[i] == 1024)     idx = d_in[i];
    }

    resolve_idx_kernel<<<1, NBATCH>>>((const int*)idx);

    const size_t smem_bytes = (NBLK * NBLK + NBLK * FEAT) * sizeof(float);  // 81920
    cudaFuncSetAttribute(bmm_kernel, cudaFuncAttributeMaxDynamicSharedMemorySize,
                         (int)smem_bytes);
    bmm_kernel<<<NBATCH, THREADS, smem_bytes>>>(inp, W, (float*)d_out);
}